// round 1
// baseline (speedup 1.0000x reference)
#include <cuda_runtime.h>
#include <stdint.h>

#define NB   296          // blocks for scan kernel (2 per SM on 148 SMs)
#define TPB  512
#define NW   (TPB / 32)
#define KTOP 16
#define NC   (NB * KTOP)  // 4736 candidates

__device__ unsigned long long g_cand[NC];

static __device__ __forceinline__ unsigned long long make_key(float d2, int idx) {
    // d2 >= 0 so its float bits are monotone as unsigned. Larger key = larger d2,
    // ties broken by SMALLER index (via ~idx), matching jax.lax.top_k.
    return (((unsigned long long)__float_as_uint(d2)) << 32) | (unsigned)(~(unsigned)idx);
}

__global__ void __launch_bounds__(TPB) locse_scan(const float* __restrict__ P,
                                                  const int* __restrict__ iptr,
                                                  int n) {
    const unsigned FULL = 0xFFFFFFFFu;
    int lane = threadIdx.x & 31;
    int wid  = threadIdx.x >> 5;
    int tid  = blockIdx.x * TPB + threadIdx.x;
    const int T = NB * TPB;

    int qi = *iptr;
    float pix = __ldg(P + (size_t)qi * 6 + 0);
    float piy = __ldg(P + (size_t)qi * 6 + 1);
    float piz = __ldg(P + (size_t)qi * 6 + 2);

    unsigned long long mykey  = 0ULL;   // lanes 0..15 hold the warp's running top-16
    unsigned long long thresh = 0ULL;   // min of the 16 (warp-uniform)

    // warp-uniform trip count: (p - lane) is the warp's base index
    for (int p = tid; p - lane < n; p += 2 * T) {
        int pa = p, pb = p + T;
        bool va = pa < n, vb = pb < n;
        unsigned long long ka = 0ULL, kb = 0ULL;
        if (va) {
            float2 xy = *(const float2*)(P + (size_t)pa * 6);
            float  z  = P[(size_t)pa * 6 + 2];
            float dx = xy.x - pix, dy = xy.y - piy, dz = z - piz;
            ka = make_key(dx * dx + dy * dy + dz * dz, pa);
        }
        if (vb) {
            float2 xy = *(const float2*)(P + (size_t)pb * 6);
            float  z  = P[(size_t)pb * 6 + 2];
            float dx = xy.x - pix, dy = xy.y - piy, dz = z - piz;
            kb = make_key(dx * dx + dy * dy + dz * dz, pb);
        }

        #pragma unroll
        for (int half = 0; half < 2; half++) {
            unsigned long long kk = half ? kb : ka;
            unsigned ballot = __ballot_sync(FULL, kk > thresh);
            while (ballot) {
                int src = __ffs(ballot) - 1;
                ballot &= ballot - 1;
                unsigned long long ck = __shfl_sync(FULL, kk, src);
                if (ck > thresh) {   // warp-uniform (thresh may have risen)
                    // argmin over lanes 0..15 of mykey
                    unsigned long long mv = (lane < 16) ? mykey : 0xFFFFFFFFFFFFFFFFULL;
                    int ml = lane;
                    #pragma unroll
                    for (int off = 8; off; off >>= 1) {
                        unsigned long long ov = __shfl_down_sync(FULL, mv, off);
                        int ol = __shfl_down_sync(FULL, ml, off);
                        if (ov < mv) { mv = ov; ml = ol; }
                    }
                    ml = __shfl_sync(FULL, ml, 0);
                    if (lane == ml) mykey = ck;
                    // new threshold = min of updated 16
                    unsigned long long t = (lane < 16) ? mykey : 0xFFFFFFFFFFFFFFFFULL;
                    #pragma unroll
                    for (int off = 8; off; off >>= 1) {
                        unsigned long long ot = __shfl_down_sync(FULL, t, off);
                        t = (ot < t) ? ot : t;
                    }
                    thresh = __shfl_sync(FULL, t, 0);
                }
            }
        }
    }

    // block merge: NW*16 = 256 candidates -> top 16 -> global
    __shared__ unsigned long long s_c[NW * KTOP];
    if (lane < KTOP) s_c[wid * KTOP + lane] = mykey;
    __syncthreads();

    if (wid == 0) {
        unsigned long long e[NW * KTOP / 32];
        #pragma unroll
        for (int j = 0; j < NW * KTOP / 32; j++) e[j] = s_c[lane + 32 * j];
        for (int r = 0; r < KTOP; r++) {
            unsigned long long lm = 0ULL; int ls = 0;
            #pragma unroll
            for (int j = 0; j < NW * KTOP / 32; j++)
                if (e[j] > lm) { lm = e[j]; ls = j; }
            unsigned long long wm = lm;
            #pragma unroll
            for (int off = 16; off; off >>= 1) {
                unsigned long long o = __shfl_xor_sync(FULL, wm, off);
                wm = (o > wm) ? o : wm;
            }
            if (lm == wm && lm != 0ULL) e[ls] = 0ULL;   // keys unique -> one clear
            if (lane == 0) g_cand[blockIdx.x * KTOP + r] = wm;
        }
    }
}

__global__ void __launch_bounds__(256) locse_final(const float* __restrict__ P,
                                                   const float* __restrict__ W,
                                                   const float* __restrict__ bb,
                                                   const int* __restrict__ iptr,
                                                   float* __restrict__ out) {
    const unsigned FULL = 0xFFFFFFFFu;
    __shared__ unsigned long long s[NC];
    __shared__ unsigned long long s_red[8];
    __shared__ unsigned long long s_top[KTOP];
    __shared__ unsigned long long s_win;

    int t = threadIdx.x, lane = t & 31, wid = t >> 5;
    for (int j = t; j < NC; j += 256) s[j] = g_cand[j];
    __syncthreads();

    for (int r = 0; r < KTOP; r++) {
        unsigned long long lm = 0ULL;
        for (int j = t; j < NC; j += 256) { unsigned long long v = s[j]; if (v > lm) lm = v; }
        #pragma unroll
        for (int off = 16; off; off >>= 1) {
            unsigned long long o = __shfl_xor_sync(FULL, lm, off);
            if (o > lm) lm = o;
        }
        if (lane == 0) s_red[wid] = lm;
        __syncthreads();
        if (t == 0) {
            unsigned long long m = 0ULL;
            #pragma unroll
            for (int w = 0; w < 8; w++) if (s_red[w] > m) m = s_red[w];
            s_win = m; s_top[r] = m;
        }
        __syncthreads();
        unsigned long long m = s_win;
        for (int j = t; j < NC; j += 256) if (s[j] == m) s[j] = 0ULL;   // unique key
        __syncthreads();
    }

    if (t < KTOP) {
        unsigned long long key = s_top[t];
        int idx = (int)(~(unsigned)(key & 0xFFFFFFFFULL));
        int qi = *iptr;
        float pix = P[(size_t)qi * 6 + 0];
        float piy = P[(size_t)qi * 6 + 1];
        float piz = P[(size_t)qi * 6 + 2];
        float nx = P[(size_t)idx * 6 + 0];
        float ny = P[(size_t)idx * 6 + 1];
        float nz = P[(size_t)idx * 6 + 2];
        float dx = pix - nx, dy = piy - ny, dz = piz - nz;
        float dist = sqrtf(dx * dx + dy * dy + dz * dz);
        float feat[10] = {pix, piy, piz, nx, ny, nz, dx, dy, dz, dist};
        out[t * 6 + 0] = nx;
        out[t * 6 + 1] = ny;
        out[t * 6 + 2] = nz;
        #pragma unroll
        for (int j = 0; j < 3; j++) {
            float acc = bb[j];
            #pragma unroll
            for (int q = 0; q < 10; q++) acc += feat[q] * W[j * 10 + q];
            out[t * 6 + 3 + j] = acc;
        }
    }
}

extern "C" void kernel_launch(void* const* d_in, const int* in_sizes, int n_in,
                              void* d_out, int out_size) {
    const float* P  = (const float*)d_in[0];
    const float* W  = (const float*)d_in[1];
    const float* b  = (const float*)d_in[2];
    const int*   ip = (const int*)d_in[3];
    float* out = (float*)d_out;
    int n = in_sizes[0] / 6;

    locse_scan<<<NB, TPB>>>(P, ip, n);
    locse_final<<<1, 256>>>(P, W, b, ip, out);
}